// round 5
// baseline (speedup 1.0000x reference)
#include <cuda_runtime.h>
#include <cstdint>

// ---------------------------------------------------------------------------
// Inverse NTT over F_P, P = 2013265921 = 15*2^27 + 1, N = 2^22, C = 4.
// Two-phase shared-memory radix-2 DIT with Montgomery-form twiddles.
// Inputs detected as int32 (evidence: rounds 3/4); output written as float32.
// ---------------------------------------------------------------------------

#define LOGN 22
#define NN   (1u << LOGN)        // 4194304
#define NH   (1u << (LOGN - 1))  // 2097152 twiddles

static constexpr unsigned int P        = 2013265921u;
static constexpr unsigned int PINV_NEG = 2013265919u; // -P^{-1} mod 2^32

// Scratch: state after stages 1..11, 4 columns packed per row (uint4).
static __device__ uint4        g_scratch[NN];   // 64 MB
static __device__ unsigned int g_tw[NH];        // 8 MB, Montgomery form
static __device__ unsigned int g_ninv_mont;

#define DT_I32 0
#define DT_I64 1
#define DT_F64 2

// twiddles[0] == 1 in every layout:
//   int32   : words [1, w1!=0]
//   int64   : words [1, 0]
//   float64 : words [0, 0x3FF00000]
__device__ __forceinline__ int detect_dt(const unsigned int* tw32) {
    unsigned int w0 = tw32[0], w1 = tw32[1];
    if (w0 == 1u) return (w1 == 0u) ? DT_I64 : DT_I32;
    return DT_F64;
}

// ---------------------------------------------------------------------------

__device__ __forceinline__ unsigned int mulmont(unsigned int a, unsigned int bR) {
    // a in [0,P), bR = b * 2^32 mod P. Returns a*b mod P, in [0,P).
    unsigned long long t = (unsigned long long)a * bR;
    unsigned int m = (unsigned int)t * PINV_NEG;
    unsigned long long s = t + (unsigned long long)m * P;
    unsigned int r = (unsigned int)(s >> 32);
    return (r >= P) ? r - P : r;
}

__device__ __forceinline__ unsigned int addmod(unsigned int a, unsigned int b) {
    unsigned int r = a + b;          // < 2P < 2^32
    return min(r, r - P);
}

__device__ __forceinline__ unsigned int submod(unsigned int a, unsigned int b) {
    unsigned int r = a - b;
    return min(r, r + P);
}

__device__ __forceinline__ void bfly(uint4& lo, uint4& hi, unsigned int T) {
    unsigned int t0 = mulmont(hi.x, T);
    unsigned int t1 = mulmont(hi.y, T);
    unsigned int t2 = mulmont(hi.z, T);
    unsigned int t3 = mulmont(hi.w, T);
    uint4 l = lo;
    lo = make_uint4(addmod(l.x, t0), addmod(l.y, t1), addmod(l.z, t2), addmod(l.w, t3));
    hi = make_uint4(submod(l.x, t0), submod(l.y, t1), submod(l.z, t2), submod(l.w, t3));
}

// ---------------------------------------------------------------------------
// Kernel 0: twiddles -> Montgomery form (w * 2^32 mod P); also n_inv.
// ---------------------------------------------------------------------------
__global__ void __launch_bounds__(512) k_prep(const void* __restrict__ vtw,
                                              const void* __restrict__ vni) {
    const unsigned int* tw32 = (const unsigned int*)vtw;
    const int dt = detect_dt(tw32);
    unsigned int i = blockIdx.x * 512u + threadIdx.x;
    if (i < NH) {
        unsigned int w;
        if (dt == DT_F64)      w = (unsigned int)(long long)((const double*)vtw)[i];
        else if (dt == DT_I64) w = tw32[2u * i];
        else                   w = tw32[i];
        g_tw[i] = (unsigned int)(((unsigned long long)w << 32) % P);
    }
    if (i == 0) {
        unsigned int v;
        if (dt == DT_F64) v = (unsigned int)(long long)((const double*)vni)[0];
        else              v = ((const unsigned int*)vni)[0]; // low word in both int layouts
        g_ninv_mont = (unsigned int)(((unsigned long long)v << 32) % P);
    }
}

// ---------------------------------------------------------------------------
// Kernel 1: bit-reversal gather + stages 1..11 (low 11 index bits).
// Block b handles positions u = b*2048 + l of the post-bit-reversal array y.
// Tile kept in bit-reversed local storage: sh[p] = y[b*2048 + rev11(p)]
//   = input_row[ p<<11 | rev11(b) ].
// Stage s pairs storage slots differing in bit (11-s); twiddle index is
// rev_{s-1}(p >> (12-s)) << (22-s).
// Scratch written contiguously: scratch[b*2048 + p] = sh[p].
// ---------------------------------------------------------------------------
__global__ void __launch_bounds__(512) k_stage1(const void* __restrict__ vin,
                                                const void* __restrict__ vtw) {
    __shared__ uint4 sh[2048];
    const int dt = detect_dt((const unsigned int*)vtw);
    const unsigned int b  = blockIdx.x;
    const unsigned int rb = __brev(b) >> 21; // rev11(b)

    #pragma unroll
    for (int r = 0; r < 4; r++) {
        unsigned int p = threadIdx.x + r * 512u;
        size_t row = ((size_t)p << 11) | rb;
        uint4 v;
        if (dt == DT_I32) {
            v = ((const uint4*)vin)[row];
        } else if (dt == DT_I64) {
            const unsigned long long* in = (const unsigned long long*)vin;
            size_t base = row << 2;
            v = make_uint4((unsigned int)in[base + 0], (unsigned int)in[base + 1],
                           (unsigned int)in[base + 2], (unsigned int)in[base + 3]);
        } else { // DT_F64
            const double2* in = (const double2*)vin;
            double2 d0 = in[row * 2 + 0];
            double2 d1 = in[row * 2 + 1];
            v = make_uint4((unsigned int)(long long)d0.x, (unsigned int)(long long)d0.y,
                           (unsigned int)(long long)d1.x, (unsigned int)(long long)d1.y);
        }
        sh[p] = v;
    }
    __syncthreads();

    #pragma unroll
    for (int s = 1; s <= 11; s++) {
        const int hs = 11 - s;
        #pragma unroll
        for (int r = 0; r < 2; r++) {
            unsigned int t  = threadIdx.x + r * 512u;          // 0..1023
            unsigned int th = t >> hs;                          // < 2^{s-1}
            unsigned int p0 = (th << (hs + 1)) | (t & ((1u << hs) - 1u));
            unsigned int p1 = p0 | (1u << hs);
            unsigned int q  = (s == 1) ? 0u : (__brev(th) >> (33 - s));
            unsigned int T  = g_tw[(size_t)q << (22 - s)];
            bfly(sh[p0], sh[p1], T);
        }
        __syncthreads();
    }

    #pragma unroll
    for (int r = 0; r < 4; r++) {
        unsigned int p = threadIdx.x + r * 512u;
        g_scratch[((size_t)b << 11) + p] = sh[p];
    }
}

// ---------------------------------------------------------------------------
// Kernel 2: stages 12..22 (high 11 bits), n_inv scale, natural-order output.
// scratch[h*2048 + c] = x_11[ h<<11 | rev11(c) ].
// Block c runs the natural-order 2048-point sub-NTT over h for column L=rev11(c).
// Twiddle for local stage sg:  ((hq<<11) + L) << (11-sg).
// Output row index: h<<11 | L.  OUTPUT IS FLOAT32 (converted), per round-4
// evidence (raw-bit writes produced the float-reinterpretation error 5e23).
// ---------------------------------------------------------------------------
__global__ void __launch_bounds__(512) k_stage2(void* __restrict__ vout,
                                                const void* __restrict__ vtw) {
    __shared__ uint4 sh[2048];
    const int dt = detect_dt((const unsigned int*)vtw);
    const unsigned int c = blockIdx.x;
    const unsigned int L = __brev(c) >> 21;   // rev11(c)

    #pragma unroll
    for (int r = 0; r < 4; r++) {
        unsigned int h = threadIdx.x + r * 512u;
        sh[h] = g_scratch[((size_t)h << 11) + c];
    }
    __syncthreads();

    #pragma unroll
    for (int sg = 1; sg <= 11; sg++) {
        const unsigned int half = 1u << (sg - 1);
        #pragma unroll
        for (int r = 0; r < 2; r++) {
            unsigned int u  = threadIdx.x + r * 512u;           // 0..1023
            unsigned int hq = u & (half - 1u);
            unsigned int h0 = ((u >> (sg - 1)) << sg) | hq;
            unsigned int h1 = h0 + half;
            unsigned int T  = g_tw[(size_t)((hq << 11) + L) << (11 - sg)];
            bfly(sh[h0], sh[h1], T);
        }
        __syncthreads();
    }

    const unsigned int ninv = g_ninv_mont;
    #pragma unroll
    for (int r = 0; r < 4; r++) {
        unsigned int h = threadIdx.x + r * 512u;
        uint4 v = sh[h];
        unsigned int o0 = mulmont(v.x, ninv);
        unsigned int o1 = mulmont(v.y, ninv);
        unsigned int o2 = mulmont(v.z, ninv);
        unsigned int o3 = mulmont(v.w, ninv);
        size_t row = ((size_t)h << 11) + L;
        if (dt == DT_I32) {
            // int32 inputs -> float32 output buffer (convert, don't bit-copy)
            ((float4*)vout)[row] = make_float4((float)(int)o0, (float)(int)o1,
                                               (float)(int)o2, (float)(int)o3);
        } else if (dt == DT_I64) {
            unsigned long long* out = (unsigned long long*)vout;
            size_t base = row << 2;
            out[base + 0] = o0; out[base + 1] = o1;
            out[base + 2] = o2; out[base + 3] = o3;
        } else { // DT_F64
            double2* out = (double2*)vout;
            out[row * 2 + 0] = make_double2((double)o0, (double)o1);
            out[row * 2 + 1] = make_double2((double)o2, (double)o3);
        }
    }
}

// ---------------------------------------------------------------------------

extern "C" void kernel_launch(void* const* d_in, const int* in_sizes, int n_in,
                              void* d_out, int out_size) {
    // Positional defaults per metadata order (input, twiddles, n_inv),
    // overridden by element-count match when unambiguous.
    const void* p_in = (n_in > 0) ? d_in[0] : nullptr;
    const void* p_tw = (n_in > 1) ? d_in[1] : nullptr;
    const void* p_ni = (n_in > 2) ? d_in[2] : nullptr;
    for (int i = 0; i < n_in; i++) {
        unsigned int sz = (unsigned int)in_sizes[i];
        if (sz == NN * 4u) p_in = d_in[i];
        else if (sz == NH) p_tw = d_in[i];
        else if (sz == 1u) p_ni = d_in[i];
    }

    k_prep  <<< NH / 512, 512 >>>(p_tw, p_ni);
    k_stage1<<< 2048, 512 >>>(p_in, p_tw);
    k_stage2<<< 2048, 512 >>>(d_out, p_tw);
    (void)out_size;
}

// round 6
// speedup vs baseline: 1.0385x; 1.0385x over previous
#include <cuda_runtime.h>
#include <cstdint>

// ---------------------------------------------------------------------------
// Inverse NTT over F_P, P = 2013265921 = 15*2^27 + 1, N = 2^22, C = 4.
// int32 inputs, float32 output (confirmed round 5, rel_err == 0).
//
// Two-phase radix-2 with:
//  * column-paired blocks -> every global access is a full 32B sector
//  * four-step twist: phase-2 stage twiddles collapse to the 4KB hot set
//    g_tw[k<<11], staged in shared; twist = w^{-L*rev11(h)} applied at load,
//    with n_inv folded in.
// ---------------------------------------------------------------------------

#define LOGN 22
#define NN   (1u << LOGN)        // 4194304
#define NH   (1u << (LOGN - 1))  // 2097152 twiddles

static constexpr unsigned int P        = 2013265921u;
static constexpr unsigned int PINV_NEG = 2013265919u;            // -P^{-1} mod 2^32
static constexpr unsigned long long Rmod = (1ull << 32) % P;     // 2^32 mod P
static constexpr unsigned int R2 = (unsigned int)((Rmod * Rmod) % P); // 2^64 mod P

// Scratch layout (uint4 rows of 4 columns):
//   SC(c0, h, j) = ((c0 << 11) + h) * 2 + j   , original column c = c0 + j*1024
static __device__ uint4        g_scratch[NN];   // 64 MB
static __device__ unsigned int g_tw[NH];        // 8 MB, Montgomery form
static __device__ unsigned int g_ninv_mont;

// ---------------------------------------------------------------------------

__device__ __forceinline__ unsigned int mulmont(unsigned int a, unsigned int bR) {
    // a in [0,P), bR = b * 2^32 mod P. Returns a*b mod P, in [0,P).
    unsigned long long t = (unsigned long long)a * bR;
    unsigned int m = (unsigned int)t * PINV_NEG;
    unsigned long long s = t + (unsigned long long)m * P;
    unsigned int r = (unsigned int)(s >> 32);
    return (r >= P) ? r - P : r;
}

__device__ __forceinline__ unsigned int addmod(unsigned int a, unsigned int b) {
    unsigned int r = a + b;
    return min(r, r - P);
}

__device__ __forceinline__ unsigned int submod(unsigned int a, unsigned int b) {
    unsigned int r = a - b;
    return min(r, r + P);
}

__device__ __forceinline__ void bfly(uint4& lo, uint4& hi, unsigned int T) {
    unsigned int t0 = mulmont(hi.x, T);
    unsigned int t1 = mulmont(hi.y, T);
    unsigned int t2 = mulmont(hi.z, T);
    unsigned int t3 = mulmont(hi.w, T);
    uint4 l = lo;
    lo = make_uint4(addmod(l.x, t0), addmod(l.y, t1), addmod(l.z, t2), addmod(l.w, t3));
    hi = make_uint4(submod(l.x, t0), submod(l.y, t1), submod(l.z, t2), submod(l.w, t3));
}

// ---------------------------------------------------------------------------
// Kernel 0: twiddles -> Montgomery form via single Montgomery mul by R^2.
// ---------------------------------------------------------------------------
__global__ void __launch_bounds__(512) k_prep(const unsigned int* __restrict__ tw,
                                              const unsigned int* __restrict__ ni) {
    unsigned int i = blockIdx.x * 512u + threadIdx.x;
    if (i < NH) g_tw[i] = mulmont(tw[i], R2);
    if (i == 0) g_ninv_mont = mulmont(ni[0], R2);
}

// ---------------------------------------------------------------------------
// Kernel 1: bit-reversal gather + stages 1..11.  Block B handles gather
// columns rb0 = 2B, rb0+1 (two tiles, shared twiddles, 32B-coalesced input).
// Tile j, slot p  <-  input[ p<<11 | (rb0+j) ].
// Stage s pairs storage slots differing in bit (11-s); twiddle
// g_tw[q<<(22-s)] = shtw[q<<(11-s)], q = rev_{s-1}(p >> (12-s)).
// Scratch write (paired layout): tile j's old row index b_j = rev11(rb0+j),
// b1 = b0 + 1024;  SC(p&1023, b_j, p>>10) = sh_j[p].
// ---------------------------------------------------------------------------
__global__ void __launch_bounds__(512) k_stage1(const uint4* __restrict__ in) {
    extern __shared__ uint4 smem[];
    uint4* sh0 = smem;
    uint4* sh1 = smem + 2048;
    unsigned int* shtw = (unsigned int*)(smem + 4096);   // 1024 entries

    const unsigned int B   = blockIdx.x;       // [0,1024)
    const unsigned int tid = threadIdx.x;
    const unsigned int rb0 = 2u * B;

    shtw[tid]        = g_tw[(size_t)tid << 11];
    shtw[tid + 512u] = g_tw[(size_t)(tid + 512u) << 11];

    #pragma unroll
    for (int r = 0; r < 4; r++) {
        unsigned int p = tid + r * 512u;
        size_t row = ((size_t)p << 11) | rb0;
        sh0[p] = in[row];
        sh1[p] = in[row + 1];
    }
    __syncthreads();

    #pragma unroll
    for (int s = 1; s <= 11; s++) {
        const int hs = 11 - s;
        #pragma unroll
        for (int r = 0; r < 2; r++) {
            unsigned int t  = tid + r * 512u;
            unsigned int th = t >> hs;
            unsigned int p0 = (th << (hs + 1)) | (t & ((1u << hs) - 1u));
            unsigned int p1 = p0 | (1u << hs);
            unsigned int q  = (s == 1) ? 0u : (__brev(th) >> (33 - s));
            unsigned int T  = shtw[q << (11 - s)];
            bfly(sh0[p0], sh0[p1], T);
            bfly(sh1[p0], sh1[p1], T);
        }
        __syncthreads();
    }

    const unsigned int b0 = __brev(rb0) >> 21;   // rev11(2B), bit0 clear -> <1024
    const unsigned int b1 = b0 | 1024u;          // rev11(2B+1)
    #pragma unroll
    for (int rr = 0; rr < 2; rr++) {
        unsigned int p = tid + rr * 512u;        // < 1024
        size_t base = ((size_t)p << 11);
        g_scratch[(base + b0) * 2 + 0] = sh0[p];
        g_scratch[(base + b0) * 2 + 1] = sh0[p + 1024u];
        g_scratch[(base + b1) * 2 + 0] = sh1[p];
        g_scratch[(base + b1) * 2 + 1] = sh1[p + 1024u];
    }
}

// ---------------------------------------------------------------------------
// Kernel 2: stages 12..22 + twist + n_inv, natural-order float32 output.
// Block C handles column pair c = C (tile0, L0 = rev11(C), even) and
// c = C+1024 (tile1, L1 = L0+1).  Loads SC(C,h,{0,1}) fully contiguous.
// Twist at load: element (h) of tile j gets  w^{-L_j * rev11(h)} * n_inv,
// built from one scattered base lookup (idx 4*L_j*rev9(tid), with the
// w^{-2^21} = -1 fold) times uniform W_j^m = mont(w^{-L_j*m}), m=rev2(k).
// Stages use plain twiddles shtw[hq<<(11-sg)].
// Output rows (h<<11|L0) and (h<<11|L1) are adjacent -> 32B stores.
// ---------------------------------------------------------------------------
__global__ void __launch_bounds__(512) k_stage2(float4* __restrict__ out) {
    extern __shared__ uint4 smem[];
    uint4* sh0 = smem;
    uint4* sh1 = smem + 2048;
    unsigned int* shtw = (unsigned int*)(smem + 4096);

    const unsigned int C   = blockIdx.x;        // [0,1024)
    const unsigned int tid = threadIdx.x;
    const unsigned int L0  = __brev(C) >> 21;   // rev11(C), even
    const unsigned int L1  = L0 + 1u;

    shtw[tid]        = g_tw[(size_t)tid << 11];
    shtw[tid + 512u] = g_tw[(size_t)(tid + 512u) << 11];

    const unsigned int ninv = g_ninv_mont;
    // uniform twist correction factors (indices < 3*2048 << 2^21: no sign fold)
    const unsigned int W0_1 = g_tw[L0],      W1_1 = g_tw[L1];
    const unsigned int W0_2 = g_tw[2u * L0], W1_2 = g_tw[2u * L1];
    const unsigned int W0_3 = g_tw[3u * L0], W1_3 = g_tw[3u * L1];

    const unsigned int r9 = __brev(tid) >> 23;  // rev9(tid)
    unsigned int Fb0, Fb1;
    {
        unsigned int e0 = 4u * L0 * r9;         // < 2^22
        unsigned int v0 = g_tw[e0 & (NH - 1u)];
        if (e0 & NH) v0 = P - v0;               // w^{-2^21} = -1
        Fb0 = mulmont(v0, ninv);                // fold n_inv into twist
        unsigned int e1 = 4u * L1 * r9;
        unsigned int v1 = g_tw[e1 & (NH - 1u)];
        if (e1 & NH) v1 = P - v1;
        Fb1 = mulmont(v1, ninv);
    }

    #pragma unroll
    for (int k = 0; k < 4; k++) {
        unsigned int h = tid + k * 512u;
        size_t base = (((size_t)C << 11) + h) * 2;
        uint4 z0 = g_scratch[base];
        uint4 z1 = g_scratch[base + 1];
        unsigned int f0, f1;                     // rev2(k): 0,2,1,3
        if      (k == 0) { f0 = Fb0;                 f1 = Fb1;                 }
        else if (k == 1) { f0 = mulmont(Fb0, W0_2);  f1 = mulmont(Fb1, W1_2);  }
        else if (k == 2) { f0 = mulmont(Fb0, W0_1);  f1 = mulmont(Fb1, W1_1);  }
        else             { f0 = mulmont(Fb0, W0_3);  f1 = mulmont(Fb1, W1_3);  }
        sh0[h] = make_uint4(mulmont(z0.x, f0), mulmont(z0.y, f0),
                            mulmont(z0.z, f0), mulmont(z0.w, f0));
        sh1[h] = make_uint4(mulmont(z1.x, f1), mulmont(z1.y, f1),
                            mulmont(z1.z, f1), mulmont(z1.w, f1));
    }
    __syncthreads();

    #pragma unroll
    for (int sg = 1; sg <= 11; sg++) {
        const unsigned int half = 1u << (sg - 1);
        #pragma unroll
        for (int r = 0; r < 2; r++) {
            unsigned int u  = tid + r * 512u;
            unsigned int hq = u & (half - 1u);
            unsigned int h0 = ((u >> (sg - 1)) << sg) | hq;
            unsigned int h1 = h0 + half;
            unsigned int T  = shtw[hq << (11 - sg)];
            bfly(sh0[h0], sh0[h1], T);
            bfly(sh1[h0], sh1[h1], T);
        }
        __syncthreads();
    }

    #pragma unroll
    for (int k = 0; k < 4; k++) {
        unsigned int h = tid + k * 512u;
        uint4 v0 = sh0[h];
        uint4 v1 = sh1[h];
        size_t row = ((size_t)h << 11) | L0;     // L0 even; L1 = row+1
        out[row] = make_float4((float)v0.x, (float)v0.y, (float)v0.z, (float)v0.w);
        out[row + 1] = make_float4((float)v1.x, (float)v1.y, (float)v1.z, (float)v1.w);
    }
}

// ---------------------------------------------------------------------------

extern "C" void kernel_launch(void* const* d_in, const int* in_sizes, int n_in,
                              void* d_out, int out_size) {
    const void* p_in = (n_in > 0) ? d_in[0] : nullptr;
    const void* p_tw = (n_in > 1) ? d_in[1] : nullptr;
    const void* p_ni = (n_in > 2) ? d_in[2] : nullptr;
    for (int i = 0; i < n_in; i++) {
        unsigned int sz = (unsigned int)in_sizes[i];
        if (sz == NN * 4u) p_in = d_in[i];
        else if (sz == NH) p_tw = d_in[i];
        else if (sz == 1u) p_ni = d_in[i];
    }

    const int smem = 2 * 2048 * (int)sizeof(uint4) + 1024 * (int)sizeof(unsigned int); // 69632
    cudaFuncSetAttribute(k_stage1, cudaFuncAttributeMaxDynamicSharedMemorySize, smem);
    cudaFuncSetAttribute(k_stage2, cudaFuncAttributeMaxDynamicSharedMemorySize, smem);

    k_prep  <<< NH / 512, 512 >>>((const unsigned int*)p_tw, (const unsigned int*)p_ni);
    k_stage1<<< 1024, 512, smem >>>((const uint4*)p_in);
    k_stage2<<< 1024, 512, smem >>>((float4*)d_out);
    (void)out_size;
}

// round 7
// speedup vs baseline: 1.3984x; 1.3467x over previous
#include <cuda_runtime.h>
#include <cstdint>

// ---------------------------------------------------------------------------
// Inverse NTT over F_P, P = 2013265921 = 15*2^27 + 1, N = 2^22, C = 4.
// int32 inputs, float32 output (confirmed: rel_err == 0 in rounds 5/6).
//
// Two-phase NTT, radix-8/4 passes in swizzled shared memory:
//   phase 1: bit-reverse gather + stages 1..11  (R8 + R4 + R8 + R8, 5 syncs)
//   phase 2: stages 12..22 via four-step twist  (R8 + R4 + R8 + R8, 5 syncs)
// Stage twiddles come from the 1024-entry decimated set g_tw[k<<11], staged
// in shared and Montgomery-converted on the fly (no prep kernel).
// ---------------------------------------------------------------------------

#define LOGN 22
#define NN   (1u << LOGN)
#define NH   (1u << (LOGN - 1))

static constexpr unsigned int P        = 2013265921u;
static constexpr unsigned int PINV_NEG = 2013265919u;                 // -P^{-1} mod 2^32
static constexpr unsigned long long Rmod = (1ull << 32) % P;
static constexpr unsigned int R2C = (unsigned int)((Rmod * Rmod) % P); // 2^64 mod P

// Scratch: slot v of phase-1 tile b at ((v&1023)<<11 + b)*2 + (v>>10).
static __device__ uint4 g_scratch[NN];   // 64 MB

// Swizzled shared index (conflict-free for all patterns used here).
__device__ __forceinline__ unsigned int SZ(unsigned int p) {
    return p ^ ((p >> 3) & 7u);
}

__device__ __forceinline__ unsigned int mulmont(unsigned int a, unsigned int bR) {
    unsigned long long t = (unsigned long long)a * bR;
    unsigned int m = (unsigned int)t * PINV_NEG;
    unsigned long long s = t + (unsigned long long)m * P;
    unsigned int r = (unsigned int)(s >> 32);
    return (r >= P) ? r - P : r;
}
__device__ __forceinline__ unsigned int addmod(unsigned int a, unsigned int b) {
    unsigned int r = a + b;  return min(r, r - P);
}
__device__ __forceinline__ unsigned int submod(unsigned int a, unsigned int b) {
    unsigned int r = a - b;  return min(r, r + P);
}

// butterfly with twiddle (hi *= T; lo,hi = lo+hi, lo-hi)
__device__ __forceinline__ void bflyT(uint4& lo, uint4& hi, unsigned int T) {
    unsigned int t0 = mulmont(hi.x, T), t1 = mulmont(hi.y, T);
    unsigned int t2 = mulmont(hi.z, T), t3 = mulmont(hi.w, T);
    uint4 l = lo;
    lo = make_uint4(addmod(l.x, t0), addmod(l.y, t1), addmod(l.z, t2), addmod(l.w, t3));
    hi = make_uint4(submod(l.x, t0), submod(l.y, t1), submod(l.z, t2), submod(l.w, t3));
}
// butterfly with T == 1 (no multiply)
__device__ __forceinline__ void bfly1(uint4& lo, uint4& hi) {
    uint4 l = lo, h = hi;
    lo = make_uint4(addmod(l.x, h.x), addmod(l.y, h.y), addmod(l.z, h.z), addmod(l.w, h.w));
    hi = make_uint4(submod(l.x, h.x), submod(l.y, h.y), submod(l.z, h.z), submod(l.w, h.w));
}

// ---------------------------------------------------------------------------
// Phase 1: gather + stages 1..11 on 2048-slot tiles in bit-reversed storage.
// Stage s acts on storage bit (11-s); T = shtw[q<<(11-s)], q = rev_{s-1}(p>>(12-s)).
// ---------------------------------------------------------------------------
__global__ void __launch_bounds__(512) k_stage1(const uint4* __restrict__ in,
                                                const unsigned int* __restrict__ tw) {
    extern __shared__ uint4 smem[];                 // 2 tiles of 2048 + shtw
    unsigned int* shtw = (unsigned int*)(smem + 4096);

    const unsigned int B   = blockIdx.x;
    const unsigned int tid = threadIdx.x;
    const unsigned int rb0 = 2u * B;

    shtw[tid]        = mulmont(tw[(size_t)tid << 11], R2C);
    shtw[tid + 512u] = mulmont(tw[(size_t)(tid + 512u) << 11], R2C);

    #pragma unroll
    for (int r = 0; r < 4; r++) {
        unsigned int p = tid + r * 512u;
        size_t row = ((size_t)p << 11) | rb0;
        smem[SZ(p)]         = in[row];
        smem[2048u + SZ(p)] = in[row + 1];
    }
    __syncthreads();

    // ---- R8a: stages 1,2,3 (bits 10,9,8); slots m + k*256 --------------
    {
        const unsigned int tb = (tid >> 8) << 11;   // tile base (0 or 2048)
        const unsigned int m  = tid & 255u;
        uint4 x[8];
        #pragma unroll
        for (int k = 0; k < 8; k++) x[k] = smem[tb + SZ(m + (k << 8))];
        const unsigned int J  = shtw[512], K1 = shtw[256], K3 = shtw[768];
        // s=1 (diff 4 in k), T=1
        bfly1(x[0], x[4]); bfly1(x[1], x[5]); bfly1(x[2], x[6]); bfly1(x[3], x[7]);
        // s=2 (diff 2): T = 1 | J by bit10
        bfly1(x[0], x[2]); bfly1(x[1], x[3]);
        bflyT(x[4], x[6], J); bflyT(x[5], x[7], J);
        // s=3 (diff 1): T = shtw[256*rev2(bits10..9)]
        bfly1(x[0], x[1]); bflyT(x[2], x[3], J);
        bflyT(x[4], x[5], K1); bflyT(x[6], x[7], K3);
        #pragma unroll
        for (int k = 0; k < 8; k++) smem[tb + SZ(m + (k << 8))] = x[k];
    }
    __syncthreads();

    // ---- R4: stages 4,5 (bits 7,6); quads {p0,+64,+128,+192} -----------
    {
        const unsigned int lo = tid & 63u, hi = tid >> 6;      // hi < 8
        const unsigned int p0 = (hi << 8) | lo;
        const unsigned int i  = (__brev(hi) >> 29) << 6;       // rev3(hi)<<6
        const unsigned int T4 = shtw[i << 1], T5a = shtw[i], T5b = shtw[i + 512u];
        #pragma unroll
        for (int t = 0; t < 2; t++) {
            const unsigned int tb = t << 11;
            uint4 x0 = smem[tb + SZ(p0)],        x1 = smem[tb + SZ(p0 + 64u)];
            uint4 x2 = smem[tb + SZ(p0 + 128u)], x3 = smem[tb + SZ(p0 + 192u)];
            bflyT(x0, x2, T4); bflyT(x1, x3, T4);              // s=4 (diff 128)
            bflyT(x0, x1, T5a); bflyT(x2, x3, T5b);            // s=5 (diff 64)
            smem[tb + SZ(p0)] = x0;        smem[tb + SZ(p0 + 64u)]  = x1;
            smem[tb + SZ(p0 + 128u)] = x2; smem[tb + SZ(p0 + 192u)] = x3;
        }
    }
    __syncthreads();

    // ---- R8b: stages 6,7,8 (bits 5,4,3); slots (hi<<6)|(k<<3)|lo3 ------
    {
        const unsigned int tb  = (tid >> 8) << 11;
        const unsigned int m   = tid & 255u;
        const unsigned int lo3 = m & 7u, hi = m >> 3;          // hi < 32
        const unsigned int vb  = (hi << 6) | lo3;
        uint4 x[8];
        #pragma unroll
        for (int k = 0; k < 8; k++) x[k] = smem[tb + SZ(vb + (k << 3))];
        const unsigned int i   = (__brev(hi) >> 27) << 5;      // rev5(hi)<<5
        const unsigned int TA  = shtw[i];
        const unsigned int TB0 = shtw[i >> 1], TB1 = shtw[(i >> 1) + 512u];
        const unsigned int ib  = i >> 2;
        const unsigned int TC0 = shtw[ib],        TC1 = shtw[ib + 512u];
        const unsigned int TC2 = shtw[ib + 256u], TC3 = shtw[ib + 768u];
        // s=6 (diff 4): all pairs TA
        bflyT(x[0], x[4], TA); bflyT(x[1], x[5], TA);
        bflyT(x[2], x[6], TA); bflyT(x[3], x[7], TA);
        // s=7 (diff 2): TB by bit5
        bflyT(x[0], x[2], TB0); bflyT(x[1], x[3], TB0);
        bflyT(x[4], x[6], TB1); bflyT(x[5], x[7], TB1);
        // s=8 (diff 1): TC_{rev2(j)} for pair j
        bflyT(x[0], x[1], TC0); bflyT(x[2], x[3], TC1);        // rev2(1)=2 -> +512
        bflyT(x[4], x[5], TC2); bflyT(x[6], x[7], TC3);
        #pragma unroll
        for (int k = 0; k < 8; k++) smem[tb + SZ(vb + (k << 3))] = x[k];
    }
    __syncthreads();

    // ---- R8c: stages 9,10,11 (bits 2,1,0); slots 8m + k ----------------
    {
        const unsigned int tb = (tid >> 8) << 11;
        const unsigned int m  = tid & 255u;
        uint4 x[8];
        #pragma unroll
        for (int k = 0; k < 8; k++) x[k] = smem[tb + SZ(8u * m + k)];
        const unsigned int i   = (__brev(m) >> 24) << 2;       // rev8(m)<<2
        const unsigned int TA  = shtw[i];
        const unsigned int TB0 = shtw[i >> 1], TB1 = shtw[(i >> 1) + 512u];
        const unsigned int ib  = i >> 2;
        const unsigned int TC0 = shtw[ib],        TC1 = shtw[ib + 512u];
        const unsigned int TC2 = shtw[ib + 256u], TC3 = shtw[ib + 768u];
        bflyT(x[0], x[4], TA); bflyT(x[1], x[5], TA);
        bflyT(x[2], x[6], TA); bflyT(x[3], x[7], TA);
        bflyT(x[0], x[2], TB0); bflyT(x[1], x[3], TB0);
        bflyT(x[4], x[6], TB1); bflyT(x[5], x[7], TB1);
        bflyT(x[0], x[1], TC0); bflyT(x[2], x[3], TC1);
        bflyT(x[4], x[5], TC2); bflyT(x[6], x[7], TC3);
        #pragma unroll
        for (int k = 0; k < 8; k++) smem[tb + SZ(8u * m + k)] = x[k];
    }
    __syncthreads();

    // ---- store: paired 32B rows into scratch ---------------------------
    const unsigned int b0 = __brev(rb0) >> 21;     // even-rb rev: < 1024
    const unsigned int b1 = b0 | 1024u;
    #pragma unroll
    for (int rr = 0; rr < 2; rr++) {
        unsigned int p = tid + rr * 512u;          // < 1024
        size_t base = ((size_t)p << 11);
        g_scratch[(base + b0) * 2 + 0] = smem[SZ(p)];
        g_scratch[(base + b0) * 2 + 1] = smem[SZ(p + 1024u)];
        g_scratch[(base + b1) * 2 + 0] = smem[2048u + SZ(p)];
        g_scratch[(base + b1) * 2 + 1] = smem[2048u + SZ(p + 1024u)];
    }
}

// ---------------------------------------------------------------------------
// Phase 2: stages 12..22 as twisted natural-order 2048-NTT per column.
// Stage sg: pairs (h, h+2^{sg-1}); T = shtw[(h & (2^{sg-1}-1)) << (11-sg)].
// Twist w^{-L*rev11(h)} * n_inv folded into load.  Tile0 = col C (L0), tile1 =
// col C+1024 (L1 = L0+1).  Output rows (h<<11|L0, +1) -> 32B stores.
// ---------------------------------------------------------------------------
__global__ void __launch_bounds__(512) k_stage2(float4* __restrict__ out,
                                                const unsigned int* __restrict__ tw,
                                                const unsigned int* __restrict__ ni) {
    extern __shared__ uint4 smem[];
    unsigned int* shtw = (unsigned int*)(smem + 4096);

    const unsigned int C   = blockIdx.x;
    const unsigned int tid = threadIdx.x;
    const unsigned int L0  = __brev(C) >> 21;      // even
    const unsigned int L1  = L0 + 1u;

    shtw[tid]        = mulmont(tw[(size_t)tid << 11], R2C);
    shtw[tid + 512u] = mulmont(tw[(size_t)(tid + 512u) << 11], R2C);

    // X = ninv * R^2 mod P  (so mulmont(raw_w, X) = mont(w * ninv))
    const unsigned int X = mulmont(mulmont(ni[0], R2C), R2C);
    const unsigned int W0_1 = mulmont(tw[L0], R2C),      W1_1 = mulmont(tw[L1], R2C);
    const unsigned int W0_2 = mulmont(tw[2u * L0], R2C), W1_2 = mulmont(tw[2u * L1], R2C);
    const unsigned int W0_3 = mulmont(tw[3u * L0], R2C), W1_3 = mulmont(tw[3u * L1], R2C);

    const unsigned int r9 = __brev(tid) >> 23;     // rev9(tid)
    unsigned int Fb0, Fb1;
    {
        unsigned int e0 = 4u * L0 * r9;            // < 2^22
        unsigned int v0 = tw[e0 & (NH - 1u)];
        if (e0 & NH) v0 = P - v0;                  // w^{-2^21} = -1 (v0 != 0)
        Fb0 = mulmont(v0, X);
        unsigned int e1 = 4u * L1 * r9;
        unsigned int v1 = tw[e1 & (NH - 1u)];
        if (e1 & NH) v1 = P - v1;
        Fb1 = mulmont(v1, X);
    }

    #pragma unroll
    for (int k = 0; k < 4; k++) {
        unsigned int h = tid + k * 512u;
        size_t base = (((size_t)C << 11) + h) * 2;
        uint4 z0 = g_scratch[base];
        uint4 z1 = g_scratch[base + 1];
        unsigned int f0, f1;                        // correction exp = rev2(k)
        if      (k == 0) { f0 = Fb0;                f1 = Fb1;                }
        else if (k == 1) { f0 = mulmont(Fb0, W0_2); f1 = mulmont(Fb1, W1_2); }
        else if (k == 2) { f0 = mulmont(Fb0, W0_1); f1 = mulmont(Fb1, W1_1); }
        else             { f0 = mulmont(Fb0, W0_3); f1 = mulmont(Fb1, W1_3); }
        smem[SZ(h)] = make_uint4(mulmont(z0.x, f0), mulmont(z0.y, f0),
                                 mulmont(z0.z, f0), mulmont(z0.w, f0));
        smem[2048u + SZ(h)] = make_uint4(mulmont(z1.x, f1), mulmont(z1.y, f1),
                                         mulmont(z1.z, f1), mulmont(z1.w, f1));
    }
    __syncthreads();

    // ---- R8a: sg 1,2,3 (strides 1,2,4); slots 8m + k -------------------
    {
        const unsigned int tb = (tid >> 8) << 11;
        const unsigned int m  = tid & 255u;
        uint4 x[8];
        #pragma unroll
        for (int k = 0; k < 8; k++) x[k] = smem[tb + SZ(8u * m + k)];
        const unsigned int J = shtw[512], K1 = shtw[256], K3 = shtw[768];
        // sg=1 (diff 1), T=1
        bfly1(x[0], x[1]); bfly1(x[2], x[3]); bfly1(x[4], x[5]); bfly1(x[6], x[7]);
        // sg=2 (diff 2): T by h&1
        bfly1(x[0], x[2]); bflyT(x[1], x[3], J);
        bfly1(x[4], x[6]); bflyT(x[5], x[7], J);
        // sg=3 (diff 4): T = shtw[(h&3)<<8]
        bfly1(x[0], x[4]); bflyT(x[1], x[5], K1);
        bflyT(x[2], x[6], J); bflyT(x[3], x[7], K3);
        #pragma unroll
        for (int k = 0; k < 8; k++) smem[tb + SZ(8u * m + k)] = x[k];
    }
    __syncthreads();

    // ---- R4: sg 4,5 (strides 8,16); quads {h0,+8,+16,+24} --------------
    {
        const unsigned int lo3 = tid & 7u, hi = tid >> 3;      // hi < 64
        const unsigned int h0  = (hi << 5) | lo3;
        const unsigned int i   = lo3 << 6;
        const unsigned int T4 = shtw[i << 1], T5a = shtw[i], T5b = shtw[i + 512u];
        #pragma unroll
        for (int t = 0; t < 2; t++) {
            const unsigned int tb = t << 11;
            uint4 x0 = smem[tb + SZ(h0)],        x1 = smem[tb + SZ(h0 + 8u)];
            uint4 x2 = smem[tb + SZ(h0 + 16u)],  x3 = smem[tb + SZ(h0 + 24u)];
            bflyT(x0, x1, T4); bflyT(x2, x3, T4);              // sg=4 (diff 8)
            bflyT(x0, x2, T5a); bflyT(x1, x3, T5b);            // sg=5 (diff 16)
            smem[tb + SZ(h0)] = x0;        smem[tb + SZ(h0 + 8u)]  = x1;
            smem[tb + SZ(h0 + 16u)] = x2;  smem[tb + SZ(h0 + 24u)] = x3;
        }
    }
    __syncthreads();

    // ---- R8b: sg 6,7,8 (strides 32,64,128); slots (hi<<8)|(k<<5)|lo5 ---
    {
        const unsigned int tb  = (tid >> 8) << 11;
        const unsigned int m   = tid & 255u;
        const unsigned int lo5 = m & 31u, hi = m >> 5;         // hi < 8
        const unsigned int vb  = (hi << 8) | lo5;
        uint4 x[8];
        #pragma unroll
        for (int k = 0; k < 8; k++) x[k] = smem[tb + SZ(vb + (k << 5))];
        const unsigned int i   = lo5 << 5;
        const unsigned int TA  = shtw[i];
        const unsigned int TB0 = shtw[i >> 1], TB1 = shtw[(i >> 1) + 512u];
        const unsigned int ib  = i >> 2;
        const unsigned int TC0 = shtw[ib],        TC1 = shtw[ib + 256u];
        const unsigned int TC2 = shtw[ib + 512u], TC3 = shtw[ib + 768u];
        // sg=6 (diff 1): all TA
        bflyT(x[0], x[1], TA); bflyT(x[2], x[3], TA);
        bflyT(x[4], x[5], TA); bflyT(x[6], x[7], TA);
        // sg=7 (diff 2): TB by k&1
        bflyT(x[0], x[2], TB0); bflyT(x[1], x[3], TB1);
        bflyT(x[4], x[6], TB0); bflyT(x[5], x[7], TB1);
        // sg=8 (diff 4): TC by k&3 (raw)
        bflyT(x[0], x[4], TC0); bflyT(x[1], x[5], TC1);
        bflyT(x[2], x[6], TC2); bflyT(x[3], x[7], TC3);
        #pragma unroll
        for (int k = 0; k < 8; k++) smem[tb + SZ(vb + (k << 5))] = x[k];
    }
    __syncthreads();

    // ---- R8c: sg 9,10,11 (strides 256,512,1024); slots (k<<8)+m --------
    {
        const unsigned int tb = (tid >> 8) << 11;
        const unsigned int m  = tid & 255u;
        uint4 x[8];
        #pragma unroll
        for (int k = 0; k < 8; k++) x[k] = smem[tb + SZ((k << 8) + m)];
        const unsigned int i   = m << 2;
        const unsigned int TA  = shtw[i];
        const unsigned int TB0 = shtw[i >> 1], TB1 = shtw[(i >> 1) + 512u];
        const unsigned int TC0 = shtw[m],        TC1 = shtw[m + 256u];
        const unsigned int TC2 = shtw[m + 512u], TC3 = shtw[m + 768u];
        bflyT(x[0], x[1], TA); bflyT(x[2], x[3], TA);
        bflyT(x[4], x[5], TA); bflyT(x[6], x[7], TA);
        bflyT(x[0], x[2], TB0); bflyT(x[1], x[3], TB1);
        bflyT(x[4], x[6], TB0); bflyT(x[5], x[7], TB1);
        bflyT(x[0], x[4], TC0); bflyT(x[1], x[5], TC1);
        bflyT(x[2], x[6], TC2); bflyT(x[3], x[7], TC3);
        #pragma unroll
        for (int k = 0; k < 8; k++) smem[tb + SZ((k << 8) + m)] = x[k];
    }
    __syncthreads();

    // ---- store: adjacent column pair -> 32B float4 x2 ------------------
    #pragma unroll
    for (int k = 0; k < 4; k++) {
        unsigned int h = tid + k * 512u;
        uint4 v0 = smem[SZ(h)];
        uint4 v1 = smem[2048u + SZ(h)];
        size_t row = ((size_t)h << 11) | L0;
        out[row]     = make_float4((float)v0.x, (float)v0.y, (float)v0.z, (float)v0.w);
        out[row + 1] = make_float4((float)v1.x, (float)v1.y, (float)v1.z, (float)v1.w);
    }
}

// ---------------------------------------------------------------------------

extern "C" void kernel_launch(void* const* d_in, const int* in_sizes, int n_in,
                              void* d_out, int out_size) {
    const void* p_in = (n_in > 0) ? d_in[0] : nullptr;
    const void* p_tw = (n_in > 1) ? d_in[1] : nullptr;
    const void* p_ni = (n_in > 2) ? d_in[2] : nullptr;
    for (int i = 0; i < n_in; i++) {
        unsigned int sz = (unsigned int)in_sizes[i];
        if (sz == NN * 4u) p_in = d_in[i];
        else if (sz == NH) p_tw = d_in[i];
        else if (sz == 1u) p_ni = d_in[i];
    }

    const int smem = 4096 * (int)sizeof(uint4) + 1024 * (int)sizeof(unsigned int); // 69632
    cudaFuncSetAttribute(k_stage1, cudaFuncAttributeMaxDynamicSharedMemorySize, smem);
    cudaFuncSetAttribute(k_stage2, cudaFuncAttributeMaxDynamicSharedMemorySize, smem);

    k_stage1<<< 1024, 512, smem >>>((const uint4*)p_in, (const unsigned int*)p_tw);
    k_stage2<<< 1024, 512, smem >>>((float4*)d_out, (const unsigned int*)p_tw,
                                    (const unsigned int*)p_ni);
    (void)out_size;
}

// round 8
// speedup vs baseline: 1.4524x; 1.0386x over previous
#include <cuda_runtime.h>
#include <cstdint>

// ---------------------------------------------------------------------------
// Inverse NTT over F_P, P = 2013265921 = 15*2^27 + 1, N = 2^22, C = 4.
// int32 inputs, float32 output (confirmed: rel_err == 0 in rounds 5/6).
//
// Two-phase NTT, radix-8/4 passes in swizzled shared memory:
//   phase 1: bit-reverse gather + stages 1..11  (R8 + R4 + R8 + R8, 5 syncs)
//   phase 2: stages 12..22 via four-step twist  (R8 + R4 + R8 + R8, 5 syncs)
// Stage twiddles come from the 1024-entry decimated set g_tw[k<<11], staged
// in shared and Montgomery-converted on the fly (no prep kernel).
// ---------------------------------------------------------------------------

#define LOGN 22
#define NN   (1u << LOGN)
#define NH   (1u << (LOGN - 1))

static constexpr unsigned int P        = 2013265921u;
static constexpr unsigned int PINV_NEG = 2013265919u;                 // -P^{-1} mod 2^32
static constexpr unsigned long long Rmod = (1ull << 32) % P;
static constexpr unsigned int R2C = (unsigned int)((Rmod * Rmod) % P); // 2^64 mod P

// Scratch: slot v of phase-1 tile b at ((v&1023)<<11 + b)*2 + (v>>10).
static __device__ uint4 g_scratch[NN];   // 64 MB

// Swizzled shared index (conflict-free for all patterns used here).
__device__ __forceinline__ unsigned int SZ(unsigned int p) {
    return p ^ ((p >> 3) & 7u);
}

__device__ __forceinline__ unsigned int mulmont(unsigned int a, unsigned int bR) {
    unsigned long long t = (unsigned long long)a * bR;
    unsigned int m = (unsigned int)t * PINV_NEG;
    unsigned long long s = t + (unsigned long long)m * P;
    unsigned int r = (unsigned int)(s >> 32);
    return (r >= P) ? r - P : r;
}
__device__ __forceinline__ unsigned int addmod(unsigned int a, unsigned int b) {
    unsigned int r = a + b;  return min(r, r - P);
}
__device__ __forceinline__ unsigned int submod(unsigned int a, unsigned int b) {
    unsigned int r = a - b;  return min(r, r + P);
}

// butterfly with twiddle (hi *= T; lo,hi = lo+hi, lo-hi)
__device__ __forceinline__ void bflyT(uint4& lo, uint4& hi, unsigned int T) {
    unsigned int t0 = mulmont(hi.x, T), t1 = mulmont(hi.y, T);
    unsigned int t2 = mulmont(hi.z, T), t3 = mulmont(hi.w, T);
    uint4 l = lo;
    lo = make_uint4(addmod(l.x, t0), addmod(l.y, t1), addmod(l.z, t2), addmod(l.w, t3));
    hi = make_uint4(submod(l.x, t0), submod(l.y, t1), submod(l.z, t2), submod(l.w, t3));
}
// butterfly with T == 1 (no multiply)
__device__ __forceinline__ void bfly1(uint4& lo, uint4& hi) {
    uint4 l = lo, h = hi;
    lo = make_uint4(addmod(l.x, h.x), addmod(l.y, h.y), addmod(l.z, h.z), addmod(l.w, h.w));
    hi = make_uint4(submod(l.x, h.x), submod(l.y, h.y), submod(l.z, h.z), submod(l.w, h.w));
}

// ---------------------------------------------------------------------------
// Phase 1: gather + stages 1..11 on 2048-slot tiles in bit-reversed storage.
// Stage s acts on storage bit (11-s); T = shtw[q<<(11-s)], q = rev_{s-1}(p>>(12-s)).
// ---------------------------------------------------------------------------
__global__ void __launch_bounds__(512) k_stage1(const uint4* __restrict__ in,
                                                const unsigned int* __restrict__ tw) {
    extern __shared__ uint4 smem[];                 // 2 tiles of 2048 + shtw
    unsigned int* shtw = (unsigned int*)(smem + 4096);

    const unsigned int B   = blockIdx.x;
    const unsigned int tid = threadIdx.x;
    const unsigned int rb0 = 2u * B;

    shtw[tid]        = mulmont(tw[(size_t)tid << 11], R2C);
    shtw[tid + 512u] = mulmont(tw[(size_t)(tid + 512u) << 11], R2C);

    #pragma unroll
    for (int r = 0; r < 4; r++) {
        unsigned int p = tid + r * 512u;
        size_t row = ((size_t)p << 11) | rb0;
        smem[SZ(p)]         = in[row];
        smem[2048u + SZ(p)] = in[row + 1];
    }
    __syncthreads();

    // ---- R8a: stages 1,2,3 (bits 10,9,8); slots m + k*256 --------------
    {
        const unsigned int tb = (tid >> 8) << 11;   // tile base (0 or 2048)
        const unsigned int m  = tid & 255u;
        uint4 x[8];
        #pragma unroll
        for (int k = 0; k < 8; k++) x[k] = smem[tb + SZ(m + (k << 8))];
        const unsigned int J  = shtw[512], K1 = shtw[256], K3 = shtw[768];
        // s=1 (diff 4 in k), T=1
        bfly1(x[0], x[4]); bfly1(x[1], x[5]); bfly1(x[2], x[6]); bfly1(x[3], x[7]);
        // s=2 (diff 2): T = 1 | J by bit10
        bfly1(x[0], x[2]); bfly1(x[1], x[3]);
        bflyT(x[4], x[6], J); bflyT(x[5], x[7], J);
        // s=3 (diff 1): T = shtw[256*rev2(bits10..9)]
        bfly1(x[0], x[1]); bflyT(x[2], x[3], J);
        bflyT(x[4], x[5], K1); bflyT(x[6], x[7], K3);
        #pragma unroll
        for (int k = 0; k < 8; k++) smem[tb + SZ(m + (k << 8))] = x[k];
    }
    __syncthreads();

    // ---- R4: stages 4,5 (bits 7,6); quads {p0,+64,+128,+192} -----------
    {
        const unsigned int lo = tid & 63u, hi = tid >> 6;      // hi < 8
        const unsigned int p0 = (hi << 8) | lo;
        const unsigned int i  = (__brev(hi) >> 29) << 6;       // rev3(hi)<<6
        const unsigned int T4 = shtw[i << 1], T5a = shtw[i], T5b = shtw[i + 512u];
        #pragma unroll
        for (int t = 0; t < 2; t++) {
            const unsigned int tb = t << 11;
            uint4 x0 = smem[tb + SZ(p0)],        x1 = smem[tb + SZ(p0 + 64u)];
            uint4 x2 = smem[tb + SZ(p0 + 128u)], x3 = smem[tb + SZ(p0 + 192u)];
            bflyT(x0, x2, T4); bflyT(x1, x3, T4);              // s=4 (diff 128)
            bflyT(x0, x1, T5a); bflyT(x2, x3, T5b);            // s=5 (diff 64)
            smem[tb + SZ(p0)] = x0;        smem[tb + SZ(p0 + 64u)]  = x1;
            smem[tb + SZ(p0 + 128u)] = x2; smem[tb + SZ(p0 + 192u)] = x3;
        }
    }
    __syncthreads();

    // ---- R8b: stages 6,7,8 (bits 5,4,3); slots (hi<<6)|(k<<3)|lo3 ------
    {
        const unsigned int tb  = (tid >> 8) << 11;
        const unsigned int m   = tid & 255u;
        const unsigned int lo3 = m & 7u, hi = m >> 3;          // hi < 32
        const unsigned int vb  = (hi << 6) | lo3;
        uint4 x[8];
        #pragma unroll
        for (int k = 0; k < 8; k++) x[k] = smem[tb + SZ(vb + (k << 3))];
        const unsigned int i   = (__brev(hi) >> 27) << 5;      // rev5(hi)<<5
        const unsigned int TA  = shtw[i];
        const unsigned int TB0 = shtw[i >> 1], TB1 = shtw[(i >> 1) + 512u];
        const unsigned int ib  = i >> 2;
        const unsigned int TC0 = shtw[ib],        TC1 = shtw[ib + 512u];
        const unsigned int TC2 = shtw[ib + 256u], TC3 = shtw[ib + 768u];
        // s=6 (diff 4): all pairs TA
        bflyT(x[0], x[4], TA); bflyT(x[1], x[5], TA);
        bflyT(x[2], x[6], TA); bflyT(x[3], x[7], TA);
        // s=7 (diff 2): TB by bit5
        bflyT(x[0], x[2], TB0); bflyT(x[1], x[3], TB0);
        bflyT(x[4], x[6], TB1); bflyT(x[5], x[7], TB1);
        // s=8 (diff 1): TC_{rev2(j)} for pair j
        bflyT(x[0], x[1], TC0); bflyT(x[2], x[3], TC1);        // rev2(1)=2 -> +512
        bflyT(x[4], x[5], TC2); bflyT(x[6], x[7], TC3);
        #pragma unroll
        for (int k = 0; k < 8; k++) smem[tb + SZ(vb + (k << 3))] = x[k];
    }
    __syncthreads();

    // ---- R8c: stages 9,10,11 (bits 2,1,0); slots 8m + k ----------------
    {
        const unsigned int tb = (tid >> 8) << 11;
        const unsigned int m  = tid & 255u;
        uint4 x[8];
        #pragma unroll
        for (int k = 0; k < 8; k++) x[k] = smem[tb + SZ(8u * m + k)];
        const unsigned int i   = (__brev(m) >> 24) << 2;       // rev8(m)<<2
        const unsigned int TA  = shtw[i];
        const unsigned int TB0 = shtw[i >> 1], TB1 = shtw[(i >> 1) + 512u];
        const unsigned int ib  = i >> 2;
        const unsigned int TC0 = shtw[ib],        TC1 = shtw[ib + 512u];
        const unsigned int TC2 = shtw[ib + 256u], TC3 = shtw[ib + 768u];
        bflyT(x[0], x[4], TA); bflyT(x[1], x[5], TA);
        bflyT(x[2], x[6], TA); bflyT(x[3], x[7], TA);
        bflyT(x[0], x[2], TB0); bflyT(x[1], x[3], TB0);
        bflyT(x[4], x[6], TB1); bflyT(x[5], x[7], TB1);
        bflyT(x[0], x[1], TC0); bflyT(x[2], x[3], TC1);
        bflyT(x[4], x[5], TC2); bflyT(x[6], x[7], TC3);
        #pragma unroll
        for (int k = 0; k < 8; k++) smem[tb + SZ(8u * m + k)] = x[k];
    }
    __syncthreads();

    // ---- store: paired 32B rows into scratch ---------------------------
    const unsigned int b0 = __brev(rb0) >> 21;     // even-rb rev: < 1024
    const unsigned int b1 = b0 | 1024u;
    #pragma unroll
    for (int rr = 0; rr < 2; rr++) {
        unsigned int p = tid + rr * 512u;          // < 1024
        size_t base = ((size_t)p << 11);
        g_scratch[(base + b0) * 2 + 0] = smem[SZ(p)];
        g_scratch[(base + b0) * 2 + 1] = smem[SZ(p + 1024u)];
        g_scratch[(base + b1) * 2 + 0] = smem[2048u + SZ(p)];
        g_scratch[(base + b1) * 2 + 1] = smem[2048u + SZ(p + 1024u)];
    }
}

// ---------------------------------------------------------------------------
// Phase 2: stages 12..22 as twisted natural-order 2048-NTT per column.
// Stage sg: pairs (h, h+2^{sg-1}); T = shtw[(h & (2^{sg-1}-1)) << (11-sg)].
// Twist w^{-L*rev11(h)} * n_inv folded into load.  Tile0 = col C (L0), tile1 =
// col C+1024 (L1 = L0+1).  Output rows (h<<11|L0, +1) -> 32B stores.
// ---------------------------------------------------------------------------
__global__ void __launch_bounds__(512) k_stage2(float4* __restrict__ out,
                                                const unsigned int* __restrict__ tw,
                                                const unsigned int* __restrict__ ni) {
    extern __shared__ uint4 smem[];
    unsigned int* shtw = (unsigned int*)(smem + 4096);

    const unsigned int C   = blockIdx.x;
    const unsigned int tid = threadIdx.x;
    const unsigned int L0  = __brev(C) >> 21;      // even
    const unsigned int L1  = L0 + 1u;

    shtw[tid]        = mulmont(tw[(size_t)tid << 11], R2C);
    shtw[tid + 512u] = mulmont(tw[(size_t)(tid + 512u) << 11], R2C);

    // X = ninv * R^2 mod P  (so mulmont(raw_w, X) = mont(w * ninv))
    const unsigned int X = mulmont(mulmont(ni[0], R2C), R2C);
    const unsigned int W0_1 = mulmont(tw[L0], R2C),      W1_1 = mulmont(tw[L1], R2C);
    const unsigned int W0_2 = mulmont(tw[2u * L0], R2C), W1_2 = mulmont(tw[2u * L1], R2C);
    const unsigned int W0_3 = mulmont(tw[3u * L0], R2C), W1_3 = mulmont(tw[3u * L1], R2C);

    const unsigned int r9 = __brev(tid) >> 23;     // rev9(tid)
    unsigned int Fb0, Fb1;
    {
        unsigned int e0 = 4u * L0 * r9;            // < 2^22
        unsigned int v0 = tw[e0 & (NH - 1u)];
        if (e0 & NH) v0 = P - v0;                  // w^{-2^21} = -1 (v0 != 0)
        Fb0 = mulmont(v0, X);
        unsigned int e1 = 4u * L1 * r9;
        unsigned int v1 = tw[e1 & (NH - 1u)];
        if (e1 & NH) v1 = P - v1;
        Fb1 = mulmont(v1, X);
    }

    #pragma unroll
    for (int k = 0; k < 4; k++) {
        unsigned int h = tid + k * 512u;
        size_t base = (((size_t)C << 11) + h) * 2;
        uint4 z0 = g_scratch[base];
        uint4 z1 = g_scratch[base + 1];
        unsigned int f0, f1;                        // correction exp = rev2(k)
        if      (k == 0) { f0 = Fb0;                f1 = Fb1;                }
        else if (k == 1) { f0 = mulmont(Fb0, W0_2); f1 = mulmont(Fb1, W1_2); }
        else if (k == 2) { f0 = mulmont(Fb0, W0_1); f1 = mulmont(Fb1, W1_1); }
        else             { f0 = mulmont(Fb0, W0_3); f1 = mulmont(Fb1, W1_3); }
        smem[SZ(h)] = make_uint4(mulmont(z0.x, f0), mulmont(z0.y, f0),
                                 mulmont(z0.z, f0), mulmont(z0.w, f0));
        smem[2048u + SZ(h)] = make_uint4(mulmont(z1.x, f1), mulmont(z1.y, f1),
                                         mulmont(z1.z, f1), mulmont(z1.w, f1));
    }
    __syncthreads();

    // ---- R8a: sg 1,2,3 (strides 1,2,4); slots 8m + k -------------------
    {
        const unsigned int tb = (tid >> 8) << 11;
        const unsigned int m  = tid & 255u;
        uint4 x[8];
        #pragma unroll
        for (int k = 0; k < 8; k++) x[k] = smem[tb + SZ(8u * m + k)];
        const unsigned int J = shtw[512], K1 = shtw[256], K3 = shtw[768];
        // sg=1 (diff 1), T=1
        bfly1(x[0], x[1]); bfly1(x[2], x[3]); bfly1(x[4], x[5]); bfly1(x[6], x[7]);
        // sg=2 (diff 2): T by h&1
        bfly1(x[0], x[2]); bflyT(x[1], x[3], J);
        bfly1(x[4], x[6]); bflyT(x[5], x[7], J);
        // sg=3 (diff 4): T = shtw[(h&3)<<8]
        bfly1(x[0], x[4]); bflyT(x[1], x[5], K1);
        bflyT(x[2], x[6], J); bflyT(x[3], x[7], K3);
        #pragma unroll
        for (int k = 0; k < 8; k++) smem[tb + SZ(8u * m + k)] = x[k];
    }
    __syncthreads();

    // ---- R4: sg 4,5 (strides 8,16); quads {h0,+8,+16,+24} --------------
    {
        const unsigned int lo3 = tid & 7u, hi = tid >> 3;      // hi < 64
        const unsigned int h0  = (hi << 5) | lo3;
        const unsigned int i   = lo3 << 6;
        const unsigned int T4 = shtw[i << 1], T5a = shtw[i], T5b = shtw[i + 512u];
        #pragma unroll
        for (int t = 0; t < 2; t++) {
            const unsigned int tb = t << 11;
            uint4 x0 = smem[tb + SZ(h0)],        x1 = smem[tb + SZ(h0 + 8u)];
            uint4 x2 = smem[tb + SZ(h0 + 16u)],  x3 = smem[tb + SZ(h0 + 24u)];
            bflyT(x0, x1, T4); bflyT(x2, x3, T4);              // sg=4 (diff 8)
            bflyT(x0, x2, T5a); bflyT(x1, x3, T5b);            // sg=5 (diff 16)
            smem[tb + SZ(h0)] = x0;        smem[tb + SZ(h0 + 8u)]  = x1;
            smem[tb + SZ(h0 + 16u)] = x2;  smem[tb + SZ(h0 + 24u)] = x3;
        }
    }
    __syncthreads();

    // ---- R8b: sg 6,7,8 (strides 32,64,128); slots (hi<<8)|(k<<5)|lo5 ---
    {
        const unsigned int tb  = (tid >> 8) << 11;
        const unsigned int m   = tid & 255u;
        const unsigned int lo5 = m & 31u, hi = m >> 5;         // hi < 8
        const unsigned int vb  = (hi << 8) | lo5;
        uint4 x[8];
        #pragma unroll
        for (int k = 0; k < 8; k++) x[k] = smem[tb + SZ(vb + (k << 5))];
        const unsigned int i   = lo5 << 5;
        const unsigned int TA  = shtw[i];
        const unsigned int TB0 = shtw[i >> 1], TB1 = shtw[(i >> 1) + 512u];
        const unsigned int ib  = i >> 2;
        const unsigned int TC0 = shtw[ib],        TC1 = shtw[ib + 256u];
        const unsigned int TC2 = shtw[ib + 512u], TC3 = shtw[ib + 768u];
        // sg=6 (diff 1): all TA
        bflyT(x[0], x[1], TA); bflyT(x[2], x[3], TA);
        bflyT(x[4], x[5], TA); bflyT(x[6], x[7], TA);
        // sg=7 (diff 2): TB by k&1
        bflyT(x[0], x[2], TB0); bflyT(x[1], x[3], TB1);
        bflyT(x[4], x[6], TB0); bflyT(x[5], x[7], TB1);
        // sg=8 (diff 4): TC by k&3 (raw)
        bflyT(x[0], x[4], TC0); bflyT(x[1], x[5], TC1);
        bflyT(x[2], x[6], TC2); bflyT(x[3], x[7], TC3);
        #pragma unroll
        for (int k = 0; k < 8; k++) smem[tb + SZ(vb + (k << 5))] = x[k];
    }
    __syncthreads();

    // ---- R8c: sg 9,10,11 (strides 256,512,1024); slots (k<<8)+m --------
    {
        const unsigned int tb = (tid >> 8) << 11;
        const unsigned int m  = tid & 255u;
        uint4 x[8];
        #pragma unroll
        for (int k = 0; k < 8; k++) x[k] = smem[tb + SZ((k << 8) + m)];
        const unsigned int i   = m << 2;
        const unsigned int TA  = shtw[i];
        const unsigned int TB0 = shtw[i >> 1], TB1 = shtw[(i >> 1) + 512u];
        const unsigned int TC0 = shtw[m],        TC1 = shtw[m + 256u];
        const unsigned int TC2 = shtw[m + 512u], TC3 = shtw[m + 768u];
        bflyT(x[0], x[1], TA); bflyT(x[2], x[3], TA);
        bflyT(x[4], x[5], TA); bflyT(x[6], x[7], TA);
        bflyT(x[0], x[2], TB0); bflyT(x[1], x[3], TB1);
        bflyT(x[4], x[6], TB0); bflyT(x[5], x[7], TB1);
        bflyT(x[0], x[4], TC0); bflyT(x[1], x[5], TC1);
        bflyT(x[2], x[6], TC2); bflyT(x[3], x[7], TC3);
        #pragma unroll
        for (int k = 0; k < 8; k++) smem[tb + SZ((k << 8) + m)] = x[k];
    }
    __syncthreads();

    // ---- store: adjacent column pair -> 32B float4 x2 ------------------
    #pragma unroll
    for (int k = 0; k < 4; k++) {
        unsigned int h = tid + k * 512u;
        uint4 v0 = smem[SZ(h)];
        uint4 v1 = smem[2048u + SZ(h)];
        size_t row = ((size_t)h << 11) | L0;
        out[row]     = make_float4((float)v0.x, (float)v0.y, (float)v0.z, (float)v0.w);
        out[row + 1] = make_float4((float)v1.x, (float)v1.y, (float)v1.z, (float)v1.w);
    }
}

// ---------------------------------------------------------------------------

extern "C" void kernel_launch(void* const* d_in, const int* in_sizes, int n_in,
                              void* d_out, int out_size) {
    const void* p_in = (n_in > 0) ? d_in[0] : nullptr;
    const void* p_tw = (n_in > 1) ? d_in[1] : nullptr;
    const void* p_ni = (n_in > 2) ? d_in[2] : nullptr;
    for (int i = 0; i < n_in; i++) {
        unsigned int sz = (unsigned int)in_sizes[i];
        if (sz == NN * 4u) p_in = d_in[i];
        else if (sz == NH) p_tw = d_in[i];
        else if (sz == 1u) p_ni = d_in[i];
    }

    const int smem = 4096 * (int)sizeof(uint4) + 1024 * (int)sizeof(unsigned int); // 69632
    cudaFuncSetAttribute(k_stage1, cudaFuncAttributeMaxDynamicSharedMemorySize, smem);
    cudaFuncSetAttribute(k_stage2, cudaFuncAttributeMaxDynamicSharedMemorySize, smem);

    k_stage1<<< 1024, 512, smem >>>((const uint4*)p_in, (const unsigned int*)p_tw);
    k_stage2<<< 1024, 512, smem >>>((float4*)d_out, (const unsigned int*)p_tw,
                                    (const unsigned int*)p_ni);
    (void)out_size;
}